// round 8
// baseline (speedup 1.0000x reference)
#include <cuda_runtime.h>
#include <math.h>

// ---------------- problem constants ----------------
constexpr int kB    = 64;
constexpr int kSVIT = 257;
constexpr int kSQ   = 32;
constexpr int kL    = 512;
constexpr int kIMG  = 1408;
constexpr int kHID  = 768;
constexpr int kC    = 30000;
constexpr int kHC   = 32;   // H_CLUB
constexpr int kHM   = 64;   // H_MINE

constexpr int kIMG4 = kIMG / 4;   // 352 float4 columns
constexpr int kHID4 = kHID / 4;   // 192 float4 columns

// phase-A block ranges
constexpr int kVitBlocks  = (kIMG4 / 32) * kB;        // 11*64 = 704
constexpr int kQBlocks    = (kHID4 / 64) * kB;        // 3*64 = 192
constexpr int kZeroBlocks = (kB * kC / 4) / 256;      // 1875
constexpr int kFrontBlocks = kVitBlocks + kQBlocks + kZeroBlocks;

// izy b-split
constexpr int kYG   = 4;          // b groups
constexpr int kBG   = kB / kYG;   // 16 b per group

// ---------------- scratch (device globals; no allocation) ----------------
__device__ __align__(16) float  g_hist[kB * kC];
__device__ __align__(16) float  g_xv[kB * kIMG];
__device__ __align__(16) float  g_xq[kB * kHID];
__device__ __align__(16) float  g_hmu[kB * kHC];
__device__ __align__(16) float  g_hlv[kB * kHC];
__device__ float  g_T0[kB];
__device__ float  g_T1[kB];
__device__ double g_acc;

__device__ __forceinline__ void f4add(float4& a, const float4 v) {
    a.x += v.x; a.y += v.y; a.z += v.z; a.w += v.w;
}

// ---------------- Phase A: vit mean | q mean | zero hist (fused) ---------
__global__ void __launch_bounds__(256) k_front(const float* __restrict__ vit,
                                               const float* __restrict__ qf) {
    int blk = blockIdx.x;
    int tid = threadIdx.x;
    __shared__ float4 sm[8][32];

    if (blk < kVitBlocks) {
        // ---- vit mean: lane ty sums s = ty, ty+8, ... ascending ----
        int bx = blk % (kIMG4 / 32);
        int b  = blk / (kIMG4 / 32);
        int tx = tid & 31, ty = tid >> 5;
        int c  = bx * 32 + tx;
        const float4* p = reinterpret_cast<const float4*>(vit)
                        + (size_t)b * kSVIT * kIMG4 + c;
        float4 a = make_float4(0.f, 0.f, 0.f, 0.f);
        #pragma unroll 4
        for (int s = ty; s < kSVIT; s += 8)
            f4add(a, p[(size_t)s * kIMG4]);
        sm[ty][tx] = a;
        __syncthreads();
        if (ty == 0) {
            float4 A0 = sm[0][tx], A1 = sm[1][tx], A2 = sm[2][tx], A3 = sm[3][tx];
            float4 A4 = sm[4][tx], A5 = sm[5][tx], A6 = sm[6][tx], A7 = sm[7][tx];
            float4 r;
            r.x = (((A0.x+A1.x)+(A2.x+A3.x)) + ((A4.x+A5.x)+(A6.x+A7.x))) / (float)kSVIT;
            r.y = (((A0.y+A1.y)+(A2.y+A3.y)) + ((A4.y+A5.y)+(A6.y+A7.y))) / (float)kSVIT;
            r.z = (((A0.z+A1.z)+(A2.z+A3.z)) + ((A4.z+A5.z)+(A6.z+A7.z))) / (float)kSVIT;
            r.w = (((A0.w+A1.w)+(A2.w+A3.w)) + ((A4.w+A5.w)+(A6.w+A7.w))) / (float)kSVIT;
            reinterpret_cast<float4*>(g_xv)[b * kIMG4 + c] = r;
        }
    } else if (blk < kVitBlocks + kQBlocks) {
        // ---- q mean: 64 columns per block (2 groups of 32), 4 s-lanes ----
        int qb = blk - kVitBlocks;
        int b  = qb / (kHID4 / 64);
        int cb = qb % (kHID4 / 64);
        int g  = tid >> 7;              // column group 0/1
        int tx = tid & 31;
        int ty = (tid >> 5) & 3;        // s-lane 0..3
        int c  = cb * 64 + g * 32 + tx;
        const float4* p = reinterpret_cast<const float4*>(qf)
                        + (size_t)b * kSQ * kHID4 + c;
        float4 a = make_float4(0.f, 0.f, 0.f, 0.f);
        #pragma unroll
        for (int s = 0; s < kSQ; s += 4)
            f4add(a, p[(size_t)(s + ty) * kHID4]);
        sm[g * 4 + ty][tx] = a;
        __syncthreads();
        if (ty == 0) {
            float4 A0 = sm[g*4+0][tx], A1 = sm[g*4+1][tx];
            float4 A2 = sm[g*4+2][tx], A3 = sm[g*4+3][tx];
            float4 r;
            r.x = ((A0.x+A1.x)+(A2.x+A3.x)) / (float)kSQ;
            r.y = ((A0.y+A1.y)+(A2.y+A3.y)) / (float)kSQ;
            r.z = ((A0.z+A1.z)+(A2.z+A3.z)) / (float)kSQ;
            r.w = ((A0.w+A1.w)+(A2.w+A3.w)) / (float)kSQ;
            reinterpret_cast<float4*>(g_xq)[b * kHID4 + c] = r;
        }
    } else {
        // ---- zero hist + acc ----
        int idx = (blk - kVitBlocks - kQBlocks) * 256 + tid;
        reinterpret_cast<float4*>(g_hist)[idx] = make_float4(0.f, 0.f, 0.f, 0.f);
        if (idx == 0) g_acc = 0.0;
    }
}

// ---------------- Phase B: scatter | CLUB head | MINE head (fused) -------
__global__ void __launch_bounds__(512) k_mid(
        const int*   __restrict__ label,
        const float* __restrict__ Wmu1, const float* __restrict__ bmu1,
        const float* __restrict__ Wlv1, const float* __restrict__ blv1,
        const float* __restrict__ Wt1,  const float* __restrict__ bt1,
        const float* __restrict__ Wt2,  const float* __restrict__ bt2,
        const int*   __restrict__ rand_idx) {
    int blk = blockIdx.x, t = threadIdx.x;

    if (blk < 64) {
        // ---- scatter: 64 blocks x 512 = kB*kL threads ----
        int i = blk * 512 + t;
        int l = label[i];
        if (l == -100) l = 0;
        atomicAdd(&g_hist[(i >> 9) * kC + l], 1.0f);   // i/kL = i>>9
    } else if (blk < 128) {
        // ---- CLUB layer 1 (4 k-lanes x 64 units; 256 active threads) ----
        int b = blk - 64;
        __shared__ float s_club[4][64];
        if (t < 256) {
            int lane = t >> 6;
            int idx  = t & 63;
            int j    = idx & 31;
            const float* W  = (idx < 32) ? Wmu1 : Wlv1;
            const float* xq = g_xq + b * kHID;
            float a = 0.f;
            for (int k = lane; k < kHID; k += 4)
                a = fmaf(xq[k], W[k * kHC + j], a);
            s_club[lane][idx] = a;
        }
        __syncthreads();
        if (t < 64) {
            int j = t & 31;
            const float* bb = (t < 32) ? bmu1 : blv1;
            float h = fmaxf(((s_club[0][t] + s_club[1][t]) +
                             (s_club[2][t] + s_club[3][t])) + bb[j], 0.f);
            if (t < 32) g_hmu[b * kHC + j] = h;
            else        g_hlv[b * kHC + j] = h;
        }
    } else {
        // ---- MINE layer 1 (4 k-lanes x 128 units) + T dot ----
        int b = blk - 128;
        __shared__ float s_mine[4][128];
        __shared__ float s_h0[kHM], s_h1[kHM];
        {
            int lane = t >> 7;            // 0..3
            int idx  = t & 127;           // which*64 + u
            int u    = idx & 63;
            int qrow = (idx < 64) ? b : rand_idx[b];
            const float* xv = g_xv + (size_t)b    * kIMG;
            const float* xq = g_xq + (size_t)qrow * kHID;
            float a = 0.f;
            for (int k = lane; k < kIMG; k += 4)
                a = fmaf(xv[k], Wt1[k * kHM + u], a);
            for (int k = lane; k < kHID; k += 4)
                a = fmaf(xq[k], Wt1[(kIMG + k) * kHM + u], a);
            s_mine[lane][idx] = a;
        }
        __syncthreads();
        if (t < 128) {
            int u = t & 63;
            float h = fmaxf(((s_mine[0][t] + s_mine[1][t]) +
                             (s_mine[2][t] + s_mine[3][t])) + bt1[u], 0.f);
            if (t < 64) s_h0[u] = h;
            else        s_h1[u] = h;
        }
        __syncthreads();
        if (t == 0) {                     // strict sequential T dot (unchanged)
            float a = 0.f, c2 = 0.f;
            for (int u = 0; u < kHM; u++) {
                float w = Wt2[u];
                a  = fmaf(s_h0[u], w, a);
                c2 = fmaf(s_h1[u], w, c2);
            }
            g_T0[b] = a  + bt2[0];
            g_T1[b] = c2 + bt2[0];
        }
    }
}

// ---------------- K5: I_zy — sparse-aware scan, b-split over grid.y ------
__global__ void __launch_bounds__(128) k_izy(
        const float* __restrict__ Wmu2, const float* __restrict__ bmu2,
        const float* __restrict__ Wlv2, const float* __restrict__ blv2,
        const int*   __restrict__ perm_idx) {
    __shared__ float s_hmu[kBG * kHC];
    __shared__ float s_hlv[kBG * kHC];
    __shared__ int   s_perm[kBG];
    int tx = threadIdx.x;
    int bbase = blockIdx.y * kBG;
    for (int i = tx; i < kBG * kHC; i += blockDim.x) {
        s_hmu[i] = g_hmu[bbase * kHC + i];
        s_hlv[i] = g_hlv[bbase * kHC + i];
    }
    if (tx < kBG) s_perm[tx] = perm_idx[bbase + tx];
    __syncthreads();

    int c = blockIdx.x * blockDim.x + tx;
    double acc = 0.0;
    if (c < kC) {
        float wm[kHC], wl[kHC];
        #pragma unroll
        for (int j = 0; j < kHC; j++) {
            wm[j] = Wmu2[j * kC + c];
            wl[j] = Wlv2[j * kC + c];
        }
        float bm = bmu2[c], bl = blv2[c];
        for (int b0 = 0; b0 < kBG; b0 += 8) {
            float ys[8], yps[8];
            #pragma unroll
            for (int j = 0; j < 8; j++) {
                ys[j]  = g_hist[(bbase + b0 + j) * kC + c];
                yps[j] = g_hist[s_perm[b0 + j] * kC + c];
            }
            #pragma unroll
            for (int q = 0; q < 8; q++) {
                int bl_i = b0 + q;        // local b
                float y = ys[q], yp = yps[q];
                if (y != 0.f || yp != 0.f) {
                    y  *= (1.f / kL);
                    yp *= (1.f / kL);
                    float mu = 0.f, lv = 0.f;
                    #pragma unroll
                    for (int j = 0; j < kHC; j++) {
                        mu = fmaf(s_hmu[bl_i * kHC + j], wm[j], mu);
                        lv = fmaf(s_hlv[bl_i * kHC + j], wl[j], lv);
                    }
                    mu += bm;
                    lv = tanhf(lv + bl);
                    float iv = 1.f / (expf(lv) + 1e-6f);
                    float dp = mu - y;
                    float dn = mu - yp;
                    acc += (double)((dn * dn - dp * dp) * iv);
                }
            }
        }
    }

    __shared__ double red[128];
    red[tx] = acc;
    __syncthreads();
    for (int s = 64; s > 0; s >>= 1) {
        if (tx < s) red[tx] += red[tx + s];
        __syncthreads();
    }
    if (tx == 0) atomicAdd(&g_acc, red[0]);
}

// ---------------- K6: finalize — parallel CR exps, strict fp32 tail ------
__global__ void k_final(float* __restrict__ out) {
    int t = threadIdx.x;                 // 64 threads
    __shared__ float s_e[kB];
    __shared__ float s_amax;

    if (t == 0) {
        float m = g_T1[0];
        for (int b = 1; b < kB; b++) m = fmaxf(m, g_T1[b]);
        s_amax = m;
    }
    __syncthreads();
    {
        float x = g_T1[t] - s_amax;
        s_e[t] = (float)exp((double)x);  // CR fp32 exp via double
    }
    __syncthreads();
    if (t == 0) {
        float esum = 0.f, t0sum = 0.f;
        for (int b = 0; b < kB; b++) {   // strict sequential fp32 sums
            esum  = esum + s_e[b];
            t0sum = t0sum + g_T0[b];
        }
        float t0m  = t0sum / 64.0f;
        float lgs  = (float)log((double)esum);
        float lse  = lgs + s_amax;
        float logB = (float)log(64.0);
        float d    = lse - logB;
        float ixz  = t0m - d;
        float izy  = (float)g_acc / 128.0f;
        out[0] = izy - 0.1f * ixz;
    }
}

// ---------------- launch ----------------
extern "C" void kernel_launch(void* const* d_in, const int* in_sizes, int n_in,
                              void* d_out, int out_size) {
    const float* vit   = (const float*)d_in[0];
    const float* qf    = (const float*)d_in[1];
    const int*   label = (const int*)  d_in[2];
    const int*   perm  = (const int*)  d_in[3];
    const int*   rnd   = (const int*)  d_in[4];
    const float* Wmu1  = (const float*)d_in[5];
    const float* bmu1  = (const float*)d_in[6];
    const float* Wmu2  = (const float*)d_in[7];
    const float* bmu2  = (const float*)d_in[8];
    const float* Wlv1  = (const float*)d_in[9];
    const float* blv1  = (const float*)d_in[10];
    const float* Wlv2  = (const float*)d_in[11];
    const float* blv2  = (const float*)d_in[12];
    const float* Wt1   = (const float*)d_in[13];
    const float* bt1   = (const float*)d_in[14];
    const float* Wt2   = (const float*)d_in[15];
    const float* bt2   = (const float*)d_in[16];
    float* out = (float*)d_out;

    k_front<<<kFrontBlocks, 256>>>(vit, qf);
    k_mid<<<192, 512>>>(label, Wmu1, bmu1, Wlv1, blv1, Wt1, bt1, Wt2, bt2, rnd);
    k_izy<<<dim3((kC + 127) / 128, kYG), 128>>>(Wmu2, bmu2, Wlv2, blv2, perm);
    k_final<<<1, 64>>>(out);
}

// round 9
// speedup vs baseline: 1.4565x; 1.4565x over previous
#include <cuda_runtime.h>
#include <math.h>

// ---------------- problem constants ----------------
constexpr int kB    = 64;
constexpr int kSVIT = 257;
constexpr int kSQ   = 32;
constexpr int kL    = 512;
constexpr int kIMG  = 1408;
constexpr int kHID  = 768;
constexpr int kC    = 30000;
constexpr int kHC   = 32;   // H_CLUB
constexpr int kHM   = 64;   // H_MINE

constexpr int kIMG4 = kIMG / 4;   // 352 float4 columns
constexpr int kHID4 = kHID / 4;   // 192 float4 columns

// izy b-split
constexpr int kYG   = 2;          // b groups
constexpr int kBG   = kB / kYG;   // 32 b per group

// ---------------- scratch (device globals; no allocation) ----------------
__device__ __align__(16) float  g_hist[kB * kC];
__device__ __align__(16) float  g_xv[kB * kIMG];
__device__ __align__(16) float  g_xq[kB * kHID];
__device__ __align__(16) float  g_hmu[kB * kHC];
__device__ __align__(16) float  g_hlv[kB * kHC];
__device__ float  g_T0[kB];
__device__ float  g_T1[kB];
__device__ double g_acc;

__device__ __forceinline__ void f4add(float4& a, const float4 v) {
    a.x += v.x; a.y += v.y; a.z += v.z; a.w += v.w;
}

// ---------------- K0: zero hist + accumulator ----------------
__global__ void k_zero() {
    int idx = blockIdx.x * blockDim.x + threadIdx.x;
    float4* p = reinterpret_cast<float4*>(g_hist);
    if (idx < (kB * kC) / 4) p[idx] = make_float4(0.f, 0.f, 0.f, 0.f);
    if (idx == 0) g_acc = 0.0;
}

// ---------------- K1: scatter labels into histogram ----------------
__global__ void k_scatter(const int* __restrict__ label) {
    int i = blockIdx.x * blockDim.x + threadIdx.x;
    if (i < kB * kL) {
        int l = label[i];
        if (l == -100) l = 0;
        int b = i / kL;
        atomicAdd(&g_hist[b * kC + l], 1.0f);
    }
}

// ---------------- K2: vit mean — 8 s-lanes/column + deep load batching ---
// Lane ty sums s = ty, ty+8, ... ascending (unroll does NOT reorder the
// single-accumulator chain; it only hoists independent loads).
// Combine tree identical to the passing kernel.
__global__ void __launch_bounds__(256) k_vit_mean(const float* __restrict__ vit) {
    int tx = threadIdx.x & 31;    // column within group
    int ty = threadIdx.x >> 5;    // s-lane 0..7
    int b  = blockIdx.y;
    int c  = blockIdx.x * 32 + tx;
    const float4* p = reinterpret_cast<const float4*>(vit) + (size_t)b * kSVIT * kIMG4 + c;
    float4 a = make_float4(0.f, 0.f, 0.f, 0.f);
    #pragma unroll 4
    for (int s = ty; s < kSVIT; s += 8)
        f4add(a, p[(size_t)s * kIMG4]);
    __shared__ float4 sm[8][32];
    sm[ty][tx] = a;
    __syncthreads();
    if (ty == 0) {
        float4 A0 = sm[0][tx], A1 = sm[1][tx], A2 = sm[2][tx], A3 = sm[3][tx];
        float4 A4 = sm[4][tx], A5 = sm[5][tx], A6 = sm[6][tx], A7 = sm[7][tx];
        float4 r;
        r.x = (((A0.x+A1.x)+(A2.x+A3.x)) + ((A4.x+A5.x)+(A6.x+A7.x))) / (float)kSVIT;
        r.y = (((A0.y+A1.y)+(A2.y+A3.y)) + ((A4.y+A5.y)+(A6.y+A7.y))) / (float)kSVIT;
        r.z = (((A0.z+A1.z)+(A2.z+A3.z)) + ((A4.z+A5.z)+(A6.z+A7.z))) / (float)kSVIT;
        r.w = (((A0.w+A1.w)+(A2.w+A3.w)) + ((A4.w+A5.w)+(A6.w+A7.w))) / (float)kSVIT;
        reinterpret_cast<float4*>(g_xv)[b * kIMG4 + c] = r;
    }
}

// ---------------- K3: qformer mean — 4 s-lanes per column, full unroll ---
__global__ void __launch_bounds__(128) k_q_mean(const float* __restrict__ qf) {
    int tx = threadIdx.x & 31;    // column within group
    int ty = threadIdx.x >> 5;    // s-lane 0..3
    int b  = blockIdx.y;
    int c  = blockIdx.x * 32 + tx;
    const float4* p = reinterpret_cast<const float4*>(qf) + (size_t)b * kSQ * kHID4 + c;
    float4 a = make_float4(0.f, 0.f, 0.f, 0.f);
    #pragma unroll
    for (int s = 0; s < kSQ; s += 4)
        f4add(a, p[(size_t)(s + ty) * kHID4]);
    __shared__ float4 sm[4][32];
    sm[ty][tx] = a;
    __syncthreads();
    if (ty == 0) {
        float4 A0 = sm[0][tx], A1 = sm[1][tx], A2 = sm[2][tx], A3 = sm[3][tx];
        float4 r;
        r.x = ((A0.x+A1.x)+(A2.x+A3.x)) / (float)kSQ;
        r.y = ((A0.y+A1.y)+(A2.y+A3.y)) / (float)kSQ;
        r.z = ((A0.z+A1.z)+(A2.z+A3.z)) / (float)kSQ;
        r.w = ((A0.w+A1.w)+(A2.w+A3.w)) / (float)kSQ;
        reinterpret_cast<float4*>(g_xq)[b * kHID4 + c] = r;
    }
}

// ---------------- K4: small MLP heads — 4 k-lanes per output unit --------
__global__ void __launch_bounds__(768) k_heads(
        const float* __restrict__ Wmu1, const float* __restrict__ bmu1,
        const float* __restrict__ Wlv1, const float* __restrict__ blv1,
        const float* __restrict__ Wt1,  const float* __restrict__ bt1,
        const float* __restrict__ Wt2,  const float* __restrict__ bt2,
        const int*   __restrict__ rand_idx) {
    int b = blockIdx.x, t = threadIdx.x;
    __shared__ float s_club[4][64];   // [lane][head*32+j]
    __shared__ float s_mine[4][128];  // [lane][which*64+u]
    __shared__ float s_h0[kHM], s_h1[kHM];

    if (t < 256) {
        int lane = t >> 6;            // k-lane 0..3
        int idx  = t & 63;            // head*32 + j
        int j    = idx & 31;
        const float* W  = (idx < 32) ? Wmu1 : Wlv1;
        const float* xq = g_xq + b * kHID;
        float a = 0.f;
        for (int k = lane; k < kHID; k += 4)
            a = fmaf(xq[k], W[k * kHC + j], a);
        s_club[lane][idx] = a;
    } else {
        int m    = t - 256;
        int lane = m >> 7;            // k-lane 0..3
        int idx  = m & 127;           // which*64 + u
        int u    = idx & 63;
        int qrow = (idx < 64) ? b : rand_idx[b];
        const float* xv = g_xv + (size_t)b    * kIMG;
        const float* xq = g_xq + (size_t)qrow * kHID;
        float a = 0.f;
        for (int k = lane; k < kIMG; k += 4)
            a = fmaf(xv[k], Wt1[k * kHM + u], a);
        for (int k = lane; k < kHID; k += 4)
            a = fmaf(xq[k], Wt1[(kIMG + k) * kHM + u], a);
        s_mine[lane][idx] = a;
    }
    __syncthreads();

    if (t < 64) {
        int j = t & 31;
        const float* bb = (t < 32) ? bmu1 : blv1;
        float h = fmaxf(((s_club[0][t] + s_club[1][t]) +
                         (s_club[2][t] + s_club[3][t])) + bb[j], 0.f);
        if (t < 32) g_hmu[b * kHC + j] = h;
        else        g_hlv[b * kHC + j] = h;
    } else if (t < 192) {
        int idx = t - 64;             // which*64 + u
        int u = idx & 63;
        float h = fmaxf(((s_mine[0][idx] + s_mine[1][idx]) +
                         (s_mine[2][idx] + s_mine[3][idx])) + bt1[u], 0.f);
        if (idx < 64) s_h0[u] = h;
        else          s_h1[u] = h;
    }
    __syncthreads();
    if (t == 0) {                     // strict sequential T dot (unchanged)
        float a = 0.f, c2 = 0.f;
        for (int u = 0; u < kHM; u++) {
            float w = Wt2[u];
            a  = fmaf(s_h0[u], w, a);
            c2 = fmaf(s_h1[u], w, c2);
        }
        g_T0[b] = a  + bt2[0];
        g_T1[b] = c2 + bt2[0];
    }
}

// ---------------- K5: I_zy — sparse-aware scan, 2-way b-split ------------
__global__ void __launch_bounds__(128) k_izy(
        const float* __restrict__ Wmu2, const float* __restrict__ bmu2,
        const float* __restrict__ Wlv2, const float* __restrict__ blv2,
        const int*   __restrict__ perm_idx) {
    __shared__ float s_hmu[kBG * kHC];
    __shared__ float s_hlv[kBG * kHC];
    __shared__ int   s_perm[kBG];
    int tx = threadIdx.x;
    int bbase = blockIdx.y * kBG;
    for (int i = tx; i < kBG * kHC; i += blockDim.x) {
        s_hmu[i] = g_hmu[bbase * kHC + i];
        s_hlv[i] = g_hlv[bbase * kHC + i];
    }
    if (tx < kBG) s_perm[tx] = perm_idx[bbase + tx];
    __syncthreads();

    int c = blockIdx.x * blockDim.x + tx;
    double acc = 0.0;
    if (c < kC) {
        float wm[kHC], wl[kHC];
        #pragma unroll
        for (int j = 0; j < kHC; j++) {
            wm[j] = Wmu2[j * kC + c];
            wl[j] = Wlv2[j * kC + c];
        }
        float bm = bmu2[c], bl = blv2[c];
        for (int b0 = 0; b0 < kBG; b0 += 8) {
            float ys[8], yps[8];
            #pragma unroll
            for (int j = 0; j < 8; j++) {
                ys[j]  = g_hist[(bbase + b0 + j) * kC + c];
                yps[j] = g_hist[s_perm[b0 + j] * kC + c];
            }
            #pragma unroll
            for (int q = 0; q < 8; q++) {
                int bl_i = b0 + q;        // local b
                float y = ys[q], yp = yps[q];
                if (y != 0.f || yp != 0.f) {
                    y  *= (1.f / kL);
                    yp *= (1.f / kL);
                    float mu = 0.f, lv = 0.f;
                    #pragma unroll
                    for (int j = 0; j < kHC; j++) {
                        mu = fmaf(s_hmu[bl_i * kHC + j], wm[j], mu);
                        lv = fmaf(s_hlv[bl_i * kHC + j], wl[j], lv);
                    }
                    mu += bm;
                    lv = tanhf(lv + bl);
                    float iv = 1.f / (expf(lv) + 1e-6f);
                    float dp = mu - y;
                    float dn = mu - yp;
                    acc += (double)((dn * dn - dp * dp) * iv);
                }
            }
        }
    }

    __shared__ double red[128];
    red[tx] = acc;
    __syncthreads();
    for (int s = 64; s > 0; s >>= 1) {
        if (tx < s) red[tx] += red[tx + s];
        __syncthreads();
    }
    if (tx == 0) atomicAdd(&g_acc, red[0]);
}

// ---------------- K6: finalize — parallel CR exps, strict fp32 tail ------
__global__ void k_final(float* __restrict__ out) {
    int t = threadIdx.x;                 // 64 threads
    __shared__ float s_e[kB];
    __shared__ float s_amax;

    if (t == 0) {
        float m = g_T1[0];
        for (int b = 1; b < kB; b++) m = fmaxf(m, g_T1[b]);
        s_amax = m;
    }
    __syncthreads();
    {
        float x = g_T1[t] - s_amax;
        s_e[t] = (float)exp((double)x);  // CR fp32 exp via double
    }
    __syncthreads();
    if (t == 0) {
        float esum = 0.f, t0sum = 0.f;
        for (int b = 0; b < kB; b++) {   // strict sequential fp32 sums
            esum  = esum + s_e[b];
            t0sum = t0sum + g_T0[b];
        }
        float t0m  = t0sum / 64.0f;
        float lgs  = (float)log((double)esum);
        float lse  = lgs + s_amax;
        float logB = (float)log(64.0);
        float d    = lse - logB;
        float ixz  = t0m - d;
        float izy  = (float)g_acc / 128.0f;
        out[0] = izy - 0.1f * ixz;
    }
}

// ---------------- launch ----------------
extern "C" void kernel_launch(void* const* d_in, const int* in_sizes, int n_in,
                              void* d_out, int out_size) {
    const float* vit   = (const float*)d_in[0];
    const float* qf    = (const float*)d_in[1];
    const int*   label = (const int*)  d_in[2];
    const int*   perm  = (const int*)  d_in[3];
    const int*   rnd   = (const int*)  d_in[4];
    const float* Wmu1  = (const float*)d_in[5];
    const float* bmu1  = (const float*)d_in[6];
    const float* Wmu2  = (const float*)d_in[7];
    const float* bmu2  = (const float*)d_in[8];
    const float* Wlv1  = (const float*)d_in[9];
    const float* blv1  = (const float*)d_in[10];
    const float* Wlv2  = (const float*)d_in[11];
    const float* blv2  = (const float*)d_in[12];
    const float* Wt1   = (const float*)d_in[13];
    const float* bt1   = (const float*)d_in[14];
    const float* Wt2   = (const float*)d_in[15];
    const float* bt2   = (const float*)d_in[16];
    float* out = (float*)d_out;

    k_zero<<<(kB * kC / 4 + 255) / 256, 256>>>();
    k_scatter<<<(kB * kL + 255) / 256, 256>>>(label);
    k_vit_mean<<<dim3(kIMG4 / 32, kB), 256>>>(vit);
    k_q_mean<<<dim3(kHID4 / 32, kB), 128>>>(qf);
    k_heads<<<kB, 768>>>(Wmu1, bmu1, Wlv1, blv1, Wt1, bt1, Wt2, bt2, rnd);
    k_izy<<<dim3((kC + 127) / 128, kYG), 128>>>(Wmu2, bmu2, Wlv2, blv2, perm);
    k_final<<<1, 64>>>(out);
}

// round 10
// speedup vs baseline: 1.6795x; 1.1531x over previous
#include <cuda_runtime.h>
#include <math.h>

// ---------------- problem constants ----------------
constexpr int kB    = 64;
constexpr int kSVIT = 257;
constexpr int kSQ   = 32;
constexpr int kL    = 512;
constexpr int kIMG  = 1408;
constexpr int kHID  = 768;
constexpr int kC    = 30000;
constexpr int kHC   = 32;   // H_CLUB
constexpr int kHM   = 64;   // H_MINE

constexpr int kIMG4 = kIMG / 4;   // 352 float4 columns
constexpr int kHID4 = kHID / 4;   // 192 float4 columns

// ---------------- scratch (device globals; no allocation) ----------------
__device__ __align__(16) float  g_hist[kB * kC];
__device__ __align__(16) float  g_xv[kB * kIMG];
__device__ __align__(16) float  g_xq[kB * kHID];
__device__ __align__(16) float  g_hmu[kB * kHC];
__device__ __align__(16) float  g_hlv[kB * kHC];
__device__ float  g_T0[kB];
__device__ float  g_T1[kB];
__device__ double g_acc;

__device__ __forceinline__ void f4add(float4& a, const float4 v) {
    a.x += v.x; a.y += v.y; a.z += v.z; a.w += v.w;
}

// ---------------- K0: zero hist + accumulator ----------------
__global__ void k_zero() {
    int idx = blockIdx.x * blockDim.x + threadIdx.x;
    float4* p = reinterpret_cast<float4*>(g_hist);
    if (idx < (kB * kC) / 4) p[idx] = make_float4(0.f, 0.f, 0.f, 0.f);
    if (idx == 0) g_acc = 0.0;
}

// ---------------- K1: scatter labels into histogram ----------------
__global__ void k_scatter(const int* __restrict__ label) {
    int i = blockIdx.x * blockDim.x + threadIdx.x;
    if (i < kB * kL) {
        int l = label[i];
        if (l == -100) l = 0;
        int b = i / kL;
        atomicAdd(&g_hist[b * kC + l], 1.0f);
    }
}

// ---------------- K2: vit mean — 8 s-lanes per column (R7 exact) ---------
__global__ void __launch_bounds__(256) k_vit_mean(const float* __restrict__ vit) {
    int tx = threadIdx.x & 31;    // column within group
    int ty = threadIdx.x >> 5;    // s-lane 0..7
    int b  = blockIdx.y;
    int c  = blockIdx.x * 32 + tx;
    const float4* p = reinterpret_cast<const float4*>(vit) + (size_t)b * kSVIT * kIMG4 + c;
    float4 a = make_float4(0.f, 0.f, 0.f, 0.f);
    for (int s = ty; s < kSVIT; s += 8)
        f4add(a, p[(size_t)s * kIMG4]);
    __shared__ float4 sm[8][32];
    sm[ty][tx] = a;
    __syncthreads();
    if (ty == 0) {
        float4 A0 = sm[0][tx], A1 = sm[1][tx], A2 = sm[2][tx], A3 = sm[3][tx];
        float4 A4 = sm[4][tx], A5 = sm[5][tx], A6 = sm[6][tx], A7 = sm[7][tx];
        float4 r;
        r.x = (((A0.x+A1.x)+(A2.x+A3.x)) + ((A4.x+A5.x)+(A6.x+A7.x))) / (float)kSVIT;
        r.y = (((A0.y+A1.y)+(A2.y+A3.y)) + ((A4.y+A5.y)+(A6.y+A7.y))) / (float)kSVIT;
        r.z = (((A0.z+A1.z)+(A2.z+A3.z)) + ((A4.z+A5.z)+(A6.z+A7.z))) / (float)kSVIT;
        r.w = (((A0.w+A1.w)+(A2.w+A3.w)) + ((A4.w+A5.w)+(A6.w+A7.w))) / (float)kSVIT;
        reinterpret_cast<float4*>(g_xv)[b * kIMG4 + c] = r;
    }
}

// ---------------- K3: qformer mean — 4 s-lanes per column (R7 exact) -----
__global__ void __launch_bounds__(128) k_q_mean(const float* __restrict__ qf) {
    int tx = threadIdx.x & 31;    // column within group
    int ty = threadIdx.x >> 5;    // s-lane 0..3
    int b  = blockIdx.y;
    int c  = blockIdx.x * 32 + tx;
    const float4* p = reinterpret_cast<const float4*>(qf) + (size_t)b * kSQ * kHID4 + c;
    float4 a = make_float4(0.f, 0.f, 0.f, 0.f);
    #pragma unroll
    for (int s = 0; s < kSQ; s += 4)
        f4add(a, p[(size_t)(s + ty) * kHID4]);
    __shared__ float4 sm[4][32];
    sm[ty][tx] = a;
    __syncthreads();
    if (ty == 0) {
        float4 A0 = sm[0][tx], A1 = sm[1][tx], A2 = sm[2][tx], A3 = sm[3][tx];
        float4 r;
        r.x = ((A0.x+A1.x)+(A2.x+A3.x)) / (float)kSQ;
        r.y = ((A0.y+A1.y)+(A2.y+A3.y)) / (float)kSQ;
        r.z = ((A0.z+A1.z)+(A2.z+A3.z)) / (float)kSQ;
        r.w = ((A0.w+A1.w)+(A2.w+A3.w)) / (float)kSQ;
        reinterpret_cast<float4*>(g_xq)[b * kHID4 + c] = r;
    }
}

// ---------------- K4: small MLP heads — 4 k-lanes per output (R7 exact) --
__global__ void __launch_bounds__(768) k_heads(
        const float* __restrict__ Wmu1, const float* __restrict__ bmu1,
        const float* __restrict__ Wlv1, const float* __restrict__ blv1,
        const float* __restrict__ Wt1,  const float* __restrict__ bt1,
        const float* __restrict__ Wt2,  const float* __restrict__ bt2,
        const int*   __restrict__ rand_idx) {
    int b = blockIdx.x, t = threadIdx.x;
    __shared__ float s_club[4][64];   // [lane][head*32+j]
    __shared__ float s_mine[4][128];  // [lane][which*64+u]
    __shared__ float s_h0[kHM], s_h1[kHM];

    if (t < 256) {
        int lane = t >> 6;            // k-lane 0..3
        int idx  = t & 63;            // head*32 + j
        int j    = idx & 31;
        const float* W  = (idx < 32) ? Wmu1 : Wlv1;
        const float* xq = g_xq + b * kHID;
        float a = 0.f;
        for (int k = lane; k < kHID; k += 4)
            a = fmaf(xq[k], W[k * kHC + j], a);
        s_club[lane][idx] = a;
    } else {
        int m    = t - 256;
        int lane = m >> 7;            // k-lane 0..3
        int idx  = m & 127;           // which*64 + u
        int u    = idx & 63;
        int qrow = (idx < 64) ? b : rand_idx[b];
        const float* xv = g_xv + (size_t)b    * kIMG;
        const float* xq = g_xq + (size_t)qrow * kHID;
        float a = 0.f;
        for (int k = lane; k < kIMG; k += 4)
            a = fmaf(xv[k], Wt1[k * kHM + u], a);
        for (int k = lane; k < kHID; k += 4)
            a = fmaf(xq[k], Wt1[(kIMG + k) * kHM + u], a);
        s_mine[lane][idx] = a;
    }
    __syncthreads();

    if (t < 64) {
        int j = t & 31;
        const float* bb = (t < 32) ? bmu1 : blv1;
        float h = fmaxf(((s_club[0][t] + s_club[1][t]) +
                         (s_club[2][t] + s_club[3][t])) + bb[j], 0.f);
        if (t < 32) g_hmu[b * kHC + j] = h;
        else        g_hlv[b * kHC + j] = h;
    } else if (t < 192) {
        int idx = t - 64;             // which*64 + u
        int u = idx & 63;
        float h = fmaxf(((s_mine[0][idx] + s_mine[1][idx]) +
                         (s_mine[2][idx] + s_mine[3][idx])) + bt1[u], 0.f);
        if (idx < 64) s_h0[u] = h;
        else          s_h1[u] = h;
    }
    __syncthreads();
    if (t == 0) {                     // strict sequential T dot (unchanged)
        float a = 0.f, c2 = 0.f;
        for (int u = 0; u < kHM; u++) {
            float w = Wt2[u];
            a  = fmaf(s_h0[u], w, a);
            c2 = fmaf(s_h1[u], w, c2);
        }
        g_T0[b] = a  + bt2[0];
        g_T1[b] = c2 + bt2[0];
    }
}

// ---------------- K5: I_zy — sparse-aware scan over (b,c) (R7 exact) -----
__global__ void __launch_bounds__(128) k_izy(
        const float* __restrict__ Wmu2, const float* __restrict__ bmu2,
        const float* __restrict__ Wlv2, const float* __restrict__ blv2,
        const int*   __restrict__ perm_idx) {
    __shared__ float s_hmu[kB * kHC];
    __shared__ float s_hlv[kB * kHC];
    __shared__ int   s_perm[kB];
    int tx = threadIdx.x;
    for (int i = tx; i < kB * kHC; i += blockDim.x) {
        s_hmu[i] = g_hmu[i];
        s_hlv[i] = g_hlv[i];
    }
    if (tx < kB) s_perm[tx] = perm_idx[tx];
    __syncthreads();

    int c = blockIdx.x * blockDim.x + tx;
    double acc = 0.0;
    if (c < kC) {
        float wm[kHC], wl[kHC];
        #pragma unroll
        for (int j = 0; j < kHC; j++) {
            wm[j] = Wmu2[j * kC + c];
            wl[j] = Wlv2[j * kC + c];
        }
        float bm = bmu2[c], bl = blv2[c];
        for (int b0 = 0; b0 < kB; b0 += 8) {
            float ys[8], yps[8];
            #pragma unroll
            for (int j = 0; j < 8; j++) {
                ys[j]  = g_hist[(b0 + j) * kC + c];
                yps[j] = g_hist[s_perm[b0 + j] * kC + c];
            }
            #pragma unroll
            for (int q = 0; q < 8; q++) {
                int b = b0 + q;
                float y = ys[q], yp = yps[q];
                if (y != 0.f || yp != 0.f) {
                    y  *= (1.f / kL);
                    yp *= (1.f / kL);
                    float mu = 0.f, lv = 0.f;
                    #pragma unroll
                    for (int j = 0; j < kHC; j++) {
                        mu = fmaf(s_hmu[b * kHC + j], wm[j], mu);
                        lv = fmaf(s_hlv[b * kHC + j], wl[j], lv);
                    }
                    mu += bm;
                    lv = tanhf(lv + bl);
                    float iv = 1.f / (expf(lv) + 1e-6f);
                    float dp = mu - y;
                    float dn = mu - yp;
                    acc += (double)((dn * dn - dp * dp) * iv);
                }
            }
        }
    }

    __shared__ double red[128];
    red[tx] = acc;
    __syncthreads();
    for (int s = 64; s > 0; s >>= 1) {
        if (tx < s) red[tx] += red[tx + s];
        __syncthreads();
    }
    if (tx == 0) atomicAdd(&g_acc, red[0]);
}

// ---------------- K6: finalize — all-parallel latency, strict fp32 tail --
__global__ void k_final(float* __restrict__ out) {
    int t = threadIdx.x;                 // 64 threads
    int lane = t & 31, warp = t >> 5;
    __shared__ float s_e[kB];
    __shared__ float s_t0[kB];
    __shared__ float s_wmax[2];

    // parallel global loads (2 loads/thread instead of 128 serial on t0)
    float t1 = g_T1[t];
    s_t0[t] = g_T0[t];

    // exact warp-shuffle amax (max is associativity-free)
    float m = t1;
    #pragma unroll
    for (int off = 16; off > 0; off >>= 1)
        m = fmaxf(m, __shfl_xor_sync(0xffffffffu, m, off));
    if (lane == 0) s_wmax[warp] = m;
    __syncthreads();
    float amax = fmaxf(s_wmax[0], s_wmax[1]);

    // parallel CR fp32 exp via double (identical values to serial version)
    s_e[t] = (float)exp((double)(t1 - amax));
    __syncthreads();

    if (t == 0) {
        // strict sequential fp32 sums — same order as passing kernel,
        // now reading shared memory (~30cyc) instead of global (~230cyc)
        float esum = 0.f, t0sum = 0.f;
        for (int b = 0; b < kB; b++) {
            esum  = esum + s_e[b];
            t0sum = t0sum + s_t0[b];
        }
        float t0m  = t0sum / 64.0f;
        float lgs  = (float)log((double)esum);
        float lse  = lgs + amax;
        float logB = (float)log(64.0);
        float d    = lse - logB;
        float ixz  = t0m - d;
        float izy  = (float)g_acc / 128.0f;
        out[0] = izy - 0.1f * ixz;
    }
}

// ---------------- launch (q before vit so vit lands in the ncu slot) -----
extern "C" void kernel_launch(void* const* d_in, const int* in_sizes, int n_in,
                              void* d_out, int out_size) {
    const float* vit   = (const float*)d_in[0];
    const float* qf    = (const float*)d_in[1];
    const int*   label = (const int*)  d_in[2];
    const int*   perm  = (const int*)  d_in[3];
    const int*   rnd   = (const int*)  d_in[4];
    const float* Wmu1  = (const float*)d_in[5];
    const float* bmu1  = (const float*)d_in[6];
    const float* Wmu2  = (const float*)d_in[7];
    const float* bmu2  = (const float*)d_in[8];
    const float* Wlv1  = (const float*)d_in[9];
    const float* blv1  = (const float*)d_in[10];
    const float* Wlv2  = (const float*)d_in[11];
    const float* blv2  = (const float*)d_in[12];
    const float* Wt1   = (const float*)d_in[13];
    const float* bt1   = (const float*)d_in[14];
    const float* Wt2   = (const float*)d_in[15];
    const float* bt2   = (const float*)d_in[16];
    float* out = (float*)d_out;

    k_zero<<<(kB * kC / 4 + 255) / 256, 256>>>();
    k_scatter<<<(kB * kL + 255) / 256, 256>>>(label);
    k_q_mean<<<dim3(kHID4 / 32, kB), 128>>>(qf);
    k_vit_mean<<<dim3(kIMG4 / 32, kB), 256>>>(vit);   // ncu capture slot (idx 3)
    k_heads<<<kB, 768>>>(Wmu1, bmu1, Wlv1, blv1, Wt1, bt1, Wt2, bt2, rnd);
    k_izy<<<(kC + 127) / 128, 128>>>(Wmu2, bmu2, Wlv2, blv2, perm);
    k_final<<<1, 64>>>(out);
}